// round 7
// baseline (speedup 1.0000x reference)
#include <cuda_runtime.h>
#include <math.h>

// ChamferLoss: B=4, N=8192, K=8 nearest neighbors, L2 norm.
// loss = mean over all (query, knn) exact distances, both directions.
//
// R6: NSPLIT=4 (1024 blocks -> ~27 warps/SM), smem tile as {xx,yy} LDS.128 +
//     {zz} LDS.64 (2 LDS/candidate), 4-way exact bitonic merge of partial top-8s.

namespace {
constexpr int B_      = 4;
constexpr int N_      = 8192;
constexpr int KNN     = 8;
constexpr int THREADS = 128;
constexpr int QPT     = 2;                     // queries per thread (one f32x2 pair)
constexpr int QPB     = THREADS * QPT;         // 256 queries per block
constexpr int NSPLIT  = 4;                     // candidate-dim split
constexpr int CANDS   = N_ / NSPLIT;           // 2048 candidates per block
constexpr int CHUNK   = 1024;                  // candidates per smem tile
constexpr int NCHUNK  = CANDS / CHUNK;         // 2
constexpr int QCHUNKS = N_ / QPB;              // 32
constexpr int BLOCKS  = B_ * 2 * QCHUNKS * NSPLIT;  // 1024
constexpr int NQTOT   = B_ * 2 * N_;           // 65536 query slots (both dirs)
constexpr int MBLOCKS = NQTOT / 256;           // 256 merge blocks
}

typedef unsigned long long ull;

__device__ __forceinline__ ull fx2_add(ull a, ull b) {
    ull r; asm("add.rn.f32x2 %0, %1, %2;" : "=l"(r) : "l"(a), "l"(b)); return r;
}
__device__ __forceinline__ ull fx2_mul(ull a, ull b) {
    ull r; asm("mul.rn.f32x2 %0, %1, %2;" : "=l"(r) : "l"(a), "l"(b)); return r;
}
__device__ __forceinline__ ull fx2_fma(ull a, ull b, ull c) {
    ull r; asm("fma.rn.f32x2 %0, %1, %2, %3;" : "=l"(r) : "l"(a), "l"(b), "l"(c)); return r;
}
__device__ __forceinline__ ull pack2(float lo, float hi) {
    return (ull)__float_as_uint(lo) | ((ull)__float_as_uint(hi) << 32);
}
__device__ __forceinline__ ull dupf(float v) {
    unsigned u = __float_as_uint(v);
    return (ull)u | ((ull)u << 32);
}

// Scratch (static device globals: no allocation).
__device__ float g_knn[NSPLIT * NQTOT * KNN];   // 8 MB: sorted partial d^2 lists
__device__ float g_partials[MBLOCKS];

__global__ __launch_bounds__(THREADS)
void chamfer_knn_kernel(const float* __restrict__ src,
                        const float* __restrict__ tgt,
                        const float* __restrict__ flow)
{
    // candidate tile: per candidate {-x,-x,-y,-y} (16B, LDS.128) + {-z,-z} (8B)
    __shared__ __align__(16) ulonglong2 sXY[CHUNK];   // 16 KB
    __shared__ __align__(16) ull        sZ[CHUNK];    //  8 KB

    const int tid    = threadIdx.x;
    const int bi     = blockIdx.x;
    const int split  = bi & (NSPLIT - 1);
    const int rest   = bi / NSPLIT;
    const int chunkq = rest % QCHUNKS;       // which 256-query slice
    const int bd     = rest / QCHUNKS;       // b*2 + dir
    const int dir    = bd & 1;               // 0: pred->tgt, 1: tgt->pred
    const int b      = bd >> 1;

    const float* __restrict__ sbase = src  + (size_t)b * N_ * 3;
    const float* __restrict__ tbase = tgt  + (size_t)b * N_ * 3;
    const float* __restrict__ fbase = flow + (size_t)b * N_ * 3;

    // ---- load this thread's two queries, packed ----
    float qx[QPT], qy[QPT], qz[QPT];
#pragma unroll
    for (int u = 0; u < QPT; ++u) {
        const int qi = chunkq * QPB + u * THREADS + tid;
        if (dir == 0) {            // query = pc_pred = src + flow
            qx[u] = sbase[3 * qi + 0] + fbase[3 * qi + 0];
            qy[u] = sbase[3 * qi + 1] + fbase[3 * qi + 1];
            qz[u] = sbase[3 * qi + 2] + fbase[3 * qi + 2];
        } else {                   // query = tgt
            qx[u] = tbase[3 * qi + 0];
            qy[u] = tbase[3 * qi + 1];
            qz[u] = tbase[3 * qi + 2];
        }
    }
    const ull qx2 = pack2(qx[0], qx[1]);
    const ull qy2 = pack2(qy[0], qy[1]);
    const ull qz2 = pack2(qz[0], qz[1]);

    // ---- per-query sorted min-8 of squared distances (ascending) ----
    float h0[KNN], h1[KNN];
#pragma unroll
    for (int i = 0; i < KNN; ++i) { h0[i] = 3.0e38f; h1[i] = 3.0e38f; }
    unsigned t0 = __float_as_uint(3.0e38f);   // bits of h0[7]
    unsigned t1 = t0;                          // bits of h1[7]

    for (int ch = 0; ch < NCHUNK; ++ch) {
        __syncthreads();   // previous tile fully consumed
        // coalesced LDG, negate, duplicate, one STS.64 per element
        const int gbase = (split * CANDS + ch * CHUNK) * 3;
        for (int t = tid; t < CHUNK * 3; t += THREADS) {
            float v;
            if (dir == 0) v = -tbase[gbase + t];                       // cands = tgt
            else          v = -(sbase[gbase + t] + fbase[gbase + t]);  // cands = pred
            const int p = t / 3;
            const int c = t - 3 * p;
            const ull d = dupf(v);
            if (c == 0)      sXY[p].x = d;
            else if (c == 1) sXY[p].y = d;
            else             sZ[p]    = d;
        }
        __syncthreads();

#pragma unroll 4
        for (int j = 0; j < CHUNK; ++j) {
            const ulonglong2 cxy = sXY[j];    // broadcast LDS.128 (pre-negated)
            const ull cz = sZ[j];             // broadcast LDS.64
            const ull dx = fx2_add(qx2, cxy.x);
            const ull dy = fx2_add(qy2, cxy.y);
            const ull dz = fx2_add(qz2, cz);
            const ull d2 = fx2_fma(dx, dx, fx2_fma(dy, dy, fx2_mul(dz, dz)));
            const unsigned d0 = (unsigned)d2;          // low half  (query 0)
            const unsigned d1 = (unsigned)(d2 >> 32);  // high half (query 1)
            // nonnegative floats: uint compare == float compare (alu pipe)
            if (__builtin_expect(d0 < t0, 0)) {
                float v = __uint_as_float(d0);
#pragma unroll
                for (int i = KNN - 1; i > 0; --i) {
                    const float hp = h0[i - 1];
                    h0[i] = fmaxf(hp, v);
                    v     = fminf(hp, v);
                }
                h0[0] = v;
                t0 = __float_as_uint(h0[KNN - 1]);
            }
            if (__builtin_expect(d1 < t1, 0)) {
                float v = __uint_as_float(d1);
#pragma unroll
                for (int i = KNN - 1; i > 0; --i) {
                    const float hp = h1[i - 1];
                    h1[i] = fmaxf(hp, v);
                    v     = fminf(hp, v);
                }
                h1[0] = v;
                t1 = __float_as_uint(h1[KNN - 1]);
            }
        }
    }

    // ---- write sorted partial lists (d^2) to global scratch ----
    const int qg0 = bd * N_ + chunkq * QPB + tid;            // query 0 global id
    const int qg1 = qg0 + THREADS;                           // query 1 global id
    float4* out0 = reinterpret_cast<float4*>(g_knn + ((size_t)split * NQTOT + qg0) * KNN);
    float4* out1 = reinterpret_cast<float4*>(g_knn + ((size_t)split * NQTOT + qg1) * KNN);
    out0[0] = make_float4(h0[0], h0[1], h0[2], h0[3]);
    out0[1] = make_float4(h0[4], h0[5], h0[6], h0[7]);
    out1[0] = make_float4(h1[0], h1[1], h1[2], h1[3]);
    out1[1] = make_float4(h1[4], h1[5], h1[6], h1[7]);
}

// --- exact branchless merge helpers ---
// halver: m[i] = min(a[i], b[7-i]); if a,b ascending, m = 8 smallest of a∪b (bitonic).
__device__ __forceinline__ void halver8(const float* __restrict__ a,
                                        const float* __restrict__ b,
                                        float* __restrict__ m)
{
#pragma unroll
    for (int i = 0; i < 8; ++i) m[i] = fminf(a[i], b[7 - i]);
}
// sort a bitonic 8-sequence ascending (3 compare-exchange stages).
__device__ __forceinline__ void bitonic_sort8(float* __restrict__ m)
{
#pragma unroll
    for (int st = 4; st > 0; st >>= 1)
#pragma unroll
        for (int i = 0; i < 8; ++i)
            if ((i & st) == 0) {
                const float lo = fminf(m[i], m[i + st]);
                const float hi = fmaxf(m[i], m[i + st]);
                m[i] = lo; m[i + st] = hi;
            }
}

// Merge 4 sorted partial top-8 lists per query, sum sqrt, deterministic reduce.
__global__ __launch_bounds__(256)
void chamfer_merge_kernel()
{
    const int qg = blockIdx.x * 256 + threadIdx.x;
    float L[NSPLIT][KNN];
#pragma unroll
    for (int sp = 0; sp < NSPLIT; ++sp) {
        const float4* p = reinterpret_cast<const float4*>(
            g_knn + ((size_t)sp * NQTOT + qg) * KNN);
        const float4 v0 = p[0], v1 = p[1];
        L[sp][0] = v0.x; L[sp][1] = v0.y; L[sp][2] = v0.z; L[sp][3] = v0.w;
        L[sp][4] = v1.x; L[sp][5] = v1.y; L[sp][6] = v1.z; L[sp][7] = v1.w;
    }

    float m01[8], m23[8], fin[8];
    halver8(L[0], L[1], m01); bitonic_sort8(m01);
    halver8(L[2], L[3], m23); bitonic_sort8(m23);
    halver8(m01, m23, fin);   // 8 smallest of all 32 (multiset; order irrelevant)

    float s = 0.0f;
#pragma unroll
    for (int i = 0; i < 8; ++i) s += sqrtf(fin[i]);

#pragma unroll
    for (int o = 16; o > 0; o >>= 1)
        s += __shfl_down_sync(0xffffffffu, s, o);

    __shared__ float ws[8];
    if ((threadIdx.x & 31) == 0) ws[threadIdx.x >> 5] = s;
    __syncthreads();
    if (threadIdx.x == 0) {
        float t = 0.0f;
#pragma unroll
        for (int i = 0; i < 8; ++i) t += ws[i];
        g_partials[blockIdx.x] = t;
    }
}

__global__ __launch_bounds__(MBLOCKS)
void chamfer_reduce_kernel(float* __restrict__ out)
{
    const int t = threadIdx.x;
    float v = g_partials[t];
#pragma unroll
    for (int o = 16; o > 0; o >>= 1)
        v += __shfl_down_sync(0xffffffffu, v, o);

    __shared__ float ws[MBLOCKS / 32];
    if ((t & 31) == 0) ws[t >> 5] = v;
    __syncthreads();
    if (t == 0) {
        float s = 0.0f;
#pragma unroll
        for (int i = 0; i < MBLOCKS / 32; ++i) s += ws[i];
        out[0] = s * (1.0f / (float)(B_ * N_ * KNN));
    }
}

extern "C" void kernel_launch(void* const* d_in, const int* in_sizes, int n_in,
                              void* d_out, int out_size)
{
    (void)in_sizes; (void)n_in; (void)out_size;
    const float* src  = (const float*)d_in[0];
    const float* tgt  = (const float*)d_in[1];
    const float* flow = (const float*)d_in[2];
    float* out = (float*)d_out;

    chamfer_knn_kernel<<<BLOCKS, THREADS>>>(src, tgt, flow);
    chamfer_merge_kernel<<<MBLOCKS, 256>>>();
    chamfer_reduce_kernel<<<1, MBLOCKS>>>(out);
}

// round 8
// speedup vs baseline: 1.0030x; 1.0030x over previous
#include <cuda_runtime.h>
#include <math.h>

// ChamferLoss: B=4, N=8192, K=8 nearest neighbors, L2 norm.
// loss = mean over all (query, knn) exact distances, both directions.
//
// R6: NSPLIT=4 (1024 blocks -> ~27 warps/SM), smem tile as {xx,yy} LDS.128 +
//     {zz} LDS.64 (2 LDS/candidate), 4-way exact bitonic merge of partial top-8s.

namespace {
constexpr int B_      = 4;
constexpr int N_      = 8192;
constexpr int KNN     = 8;
constexpr int THREADS = 128;
constexpr int QPT     = 2;                     // queries per thread (one f32x2 pair)
constexpr int QPB     = THREADS * QPT;         // 256 queries per block
constexpr int NSPLIT  = 4;                     // candidate-dim split
constexpr int CANDS   = N_ / NSPLIT;           // 2048 candidates per block
constexpr int CHUNK   = 1024;                  // candidates per smem tile
constexpr int NCHUNK  = CANDS / CHUNK;         // 2
constexpr int QCHUNKS = N_ / QPB;              // 32
constexpr int BLOCKS  = B_ * 2 * QCHUNKS * NSPLIT;  // 1024
constexpr int NQTOT   = B_ * 2 * N_;           // 65536 query slots (both dirs)
constexpr int MBLOCKS = NQTOT / 256;           // 256 merge blocks
}

typedef unsigned long long ull;

__device__ __forceinline__ ull fx2_add(ull a, ull b) {
    ull r; asm("add.rn.f32x2 %0, %1, %2;" : "=l"(r) : "l"(a), "l"(b)); return r;
}
__device__ __forceinline__ ull fx2_mul(ull a, ull b) {
    ull r; asm("mul.rn.f32x2 %0, %1, %2;" : "=l"(r) : "l"(a), "l"(b)); return r;
}
__device__ __forceinline__ ull fx2_fma(ull a, ull b, ull c) {
    ull r; asm("fma.rn.f32x2 %0, %1, %2, %3;" : "=l"(r) : "l"(a), "l"(b), "l"(c)); return r;
}
__device__ __forceinline__ ull pack2(float lo, float hi) {
    return (ull)__float_as_uint(lo) | ((ull)__float_as_uint(hi) << 32);
}
__device__ __forceinline__ ull dupf(float v) {
    unsigned u = __float_as_uint(v);
    return (ull)u | ((ull)u << 32);
}

// Scratch (static device globals: no allocation).
__device__ float g_knn[NSPLIT * NQTOT * KNN];   // 8 MB: sorted partial d^2 lists
__device__ float g_partials[MBLOCKS];

__global__ __launch_bounds__(THREADS)
void chamfer_knn_kernel(const float* __restrict__ src,
                        const float* __restrict__ tgt,
                        const float* __restrict__ flow)
{
    // candidate tile: per candidate {-x,-x,-y,-y} (16B, LDS.128) + {-z,-z} (8B)
    __shared__ __align__(16) ulonglong2 sXY[CHUNK];   // 16 KB
    __shared__ __align__(16) ull        sZ[CHUNK];    //  8 KB

    const int tid    = threadIdx.x;
    const int bi     = blockIdx.x;
    const int split  = bi & (NSPLIT - 1);
    const int rest   = bi / NSPLIT;
    const int chunkq = rest % QCHUNKS;       // which 256-query slice
    const int bd     = rest / QCHUNKS;       // b*2 + dir
    const int dir    = bd & 1;               // 0: pred->tgt, 1: tgt->pred
    const int b      = bd >> 1;

    const float* __restrict__ sbase = src  + (size_t)b * N_ * 3;
    const float* __restrict__ tbase = tgt  + (size_t)b * N_ * 3;
    const float* __restrict__ fbase = flow + (size_t)b * N_ * 3;

    // ---- load this thread's two queries, packed ----
    float qx[QPT], qy[QPT], qz[QPT];
#pragma unroll
    for (int u = 0; u < QPT; ++u) {
        const int qi = chunkq * QPB + u * THREADS + tid;
        if (dir == 0) {            // query = pc_pred = src + flow
            qx[u] = sbase[3 * qi + 0] + fbase[3 * qi + 0];
            qy[u] = sbase[3 * qi + 1] + fbase[3 * qi + 1];
            qz[u] = sbase[3 * qi + 2] + fbase[3 * qi + 2];
        } else {                   // query = tgt
            qx[u] = tbase[3 * qi + 0];
            qy[u] = tbase[3 * qi + 1];
            qz[u] = tbase[3 * qi + 2];
        }
    }
    const ull qx2 = pack2(qx[0], qx[1]);
    const ull qy2 = pack2(qy[0], qy[1]);
    const ull qz2 = pack2(qz[0], qz[1]);

    // ---- per-query sorted min-8 of squared distances (ascending) ----
    float h0[KNN], h1[KNN];
#pragma unroll
    for (int i = 0; i < KNN; ++i) { h0[i] = 3.0e38f; h1[i] = 3.0e38f; }
    unsigned t0 = __float_as_uint(3.0e38f);   // bits of h0[7]
    unsigned t1 = t0;                          // bits of h1[7]

    for (int ch = 0; ch < NCHUNK; ++ch) {
        __syncthreads();   // previous tile fully consumed
        // coalesced LDG, negate, duplicate, one STS.64 per element
        const int gbase = (split * CANDS + ch * CHUNK) * 3;
        for (int t = tid; t < CHUNK * 3; t += THREADS) {
            float v;
            if (dir == 0) v = -tbase[gbase + t];                       // cands = tgt
            else          v = -(sbase[gbase + t] + fbase[gbase + t]);  // cands = pred
            const int p = t / 3;
            const int c = t - 3 * p;
            const ull d = dupf(v);
            if (c == 0)      sXY[p].x = d;
            else if (c == 1) sXY[p].y = d;
            else             sZ[p]    = d;
        }
        __syncthreads();

#pragma unroll 4
        for (int j = 0; j < CHUNK; ++j) {
            const ulonglong2 cxy = sXY[j];    // broadcast LDS.128 (pre-negated)
            const ull cz = sZ[j];             // broadcast LDS.64
            const ull dx = fx2_add(qx2, cxy.x);
            const ull dy = fx2_add(qy2, cxy.y);
            const ull dz = fx2_add(qz2, cz);
            const ull d2 = fx2_fma(dx, dx, fx2_fma(dy, dy, fx2_mul(dz, dz)));
            const unsigned d0 = (unsigned)d2;          // low half  (query 0)
            const unsigned d1 = (unsigned)(d2 >> 32);  // high half (query 1)
            // nonnegative floats: uint compare == float compare (alu pipe)
            if (__builtin_expect(d0 < t0, 0)) {
                float v = __uint_as_float(d0);
#pragma unroll
                for (int i = KNN - 1; i > 0; --i) {
                    const float hp = h0[i - 1];
                    h0[i] = fmaxf(hp, v);
                    v     = fminf(hp, v);
                }
                h0[0] = v;
                t0 = __float_as_uint(h0[KNN - 1]);
            }
            if (__builtin_expect(d1 < t1, 0)) {
                float v = __uint_as_float(d1);
#pragma unroll
                for (int i = KNN - 1; i > 0; --i) {
                    const float hp = h1[i - 1];
                    h1[i] = fmaxf(hp, v);
                    v     = fminf(hp, v);
                }
                h1[0] = v;
                t1 = __float_as_uint(h1[KNN - 1]);
            }
        }
    }

    // ---- write sorted partial lists (d^2) to global scratch ----
    const int qg0 = bd * N_ + chunkq * QPB + tid;            // query 0 global id
    const int qg1 = qg0 + THREADS;                           // query 1 global id
    float4* out0 = reinterpret_cast<float4*>(g_knn + ((size_t)split * NQTOT + qg0) * KNN);
    float4* out1 = reinterpret_cast<float4*>(g_knn + ((size_t)split * NQTOT + qg1) * KNN);
    out0[0] = make_float4(h0[0], h0[1], h0[2], h0[3]);
    out0[1] = make_float4(h0[4], h0[5], h0[6], h0[7]);
    out1[0] = make_float4(h1[0], h1[1], h1[2], h1[3]);
    out1[1] = make_float4(h1[4], h1[5], h1[6], h1[7]);
}

// --- exact branchless merge helpers ---
// halver: m[i] = min(a[i], b[7-i]); if a,b ascending, m = 8 smallest of a∪b (bitonic).
__device__ __forceinline__ void halver8(const float* __restrict__ a,
                                        const float* __restrict__ b,
                                        float* __restrict__ m)
{
#pragma unroll
    for (int i = 0; i < 8; ++i) m[i] = fminf(a[i], b[7 - i]);
}
// sort a bitonic 8-sequence ascending (3 compare-exchange stages).
__device__ __forceinline__ void bitonic_sort8(float* __restrict__ m)
{
#pragma unroll
    for (int st = 4; st > 0; st >>= 1)
#pragma unroll
        for (int i = 0; i < 8; ++i)
            if ((i & st) == 0) {
                const float lo = fminf(m[i], m[i + st]);
                const float hi = fmaxf(m[i], m[i + st]);
                m[i] = lo; m[i + st] = hi;
            }
}

// Merge 4 sorted partial top-8 lists per query, sum sqrt, deterministic reduce.
__global__ __launch_bounds__(256)
void chamfer_merge_kernel()
{
    const int qg = blockIdx.x * 256 + threadIdx.x;
    float L[NSPLIT][KNN];
#pragma unroll
    for (int sp = 0; sp < NSPLIT; ++sp) {
        const float4* p = reinterpret_cast<const float4*>(
            g_knn + ((size_t)sp * NQTOT + qg) * KNN);
        const float4 v0 = p[0], v1 = p[1];
        L[sp][0] = v0.x; L[sp][1] = v0.y; L[sp][2] = v0.z; L[sp][3] = v0.w;
        L[sp][4] = v1.x; L[sp][5] = v1.y; L[sp][6] = v1.z; L[sp][7] = v1.w;
    }

    float m01[8], m23[8], fin[8];
    halver8(L[0], L[1], m01); bitonic_sort8(m01);
    halver8(L[2], L[3], m23); bitonic_sort8(m23);
    halver8(m01, m23, fin);   // 8 smallest of all 32 (multiset; order irrelevant)

    float s = 0.0f;
#pragma unroll
    for (int i = 0; i < 8; ++i) s += sqrtf(fin[i]);

#pragma unroll
    for (int o = 16; o > 0; o >>= 1)
        s += __shfl_down_sync(0xffffffffu, s, o);

    __shared__ float ws[8];
    if ((threadIdx.x & 31) == 0) ws[threadIdx.x >> 5] = s;
    __syncthreads();
    if (threadIdx.x == 0) {
        float t = 0.0f;
#pragma unroll
        for (int i = 0; i < 8; ++i) t += ws[i];
        g_partials[blockIdx.x] = t;
    }
}

__global__ __launch_bounds__(MBLOCKS)
void chamfer_reduce_kernel(float* __restrict__ out)
{
    const int t = threadIdx.x;
    float v = g_partials[t];
#pragma unroll
    for (int o = 16; o > 0; o >>= 1)
        v += __shfl_down_sync(0xffffffffu, v, o);

    __shared__ float ws[MBLOCKS / 32];
    if ((t & 31) == 0) ws[t >> 5] = v;
    __syncthreads();
    if (t == 0) {
        float s = 0.0f;
#pragma unroll
        for (int i = 0; i < MBLOCKS / 32; ++i) s += ws[i];
        out[0] = s * (1.0f / (float)(B_ * N_ * KNN));
    }
}

extern "C" void kernel_launch(void* const* d_in, const int* in_sizes, int n_in,
                              void* d_out, int out_size)
{
    (void)in_sizes; (void)n_in; (void)out_size;
    const float* src  = (const float*)d_in[0];
    const float* tgt  = (const float*)d_in[1];
    const float* flow = (const float*)d_in[2];
    float* out = (float*)d_out;

    chamfer_knn_kernel<<<BLOCKS, THREADS>>>(src, tgt, flow);
    chamfer_merge_kernel<<<MBLOCKS, 256>>>();
    chamfer_reduce_kernel<<<1, MBLOCKS>>>(out);
}

// round 9
// speedup vs baseline: 1.0861x; 1.0828x over previous
#include <cuda_runtime.h>
#include <math.h>

// ChamferLoss: B=4, N=8192, K=8 nearest neighbors, L2 norm.
// loss = mean over all (query, knn) exact distances, both directions.
//
// R9: Morton-sort queries per (batch,set) so warp lanes are spatially
//     coherent -> top-8 inserts fire together -> warp-union insert flood
//     collapses (~788 -> ~250 bodies/branch/warp). Brute-force scan,
//     NSPLIT=4, f32x2 packed math, exact bitonic 4-way merge.

namespace {
constexpr int B_      = 4;
constexpr int N_      = 8192;
constexpr int KNN     = 8;
constexpr int THREADS = 128;
constexpr int QPT     = 2;                     // queries per thread (one f32x2 pair)
constexpr int QPB     = THREADS * QPT;         // 256 queries per block
constexpr int NSPLIT  = 4;                     // candidate-dim split
constexpr int CANDS   = N_ / NSPLIT;           // 2048 candidates per block
constexpr int CHUNK   = 1024;                  // candidates per smem tile
constexpr int NCHUNK  = CANDS / CHUNK;         // 2
constexpr int QCHUNKS = N_ / QPB;              // 32
constexpr int BLOCKS  = B_ * 2 * QCHUNKS * NSPLIT;  // 1024
constexpr int NQTOT   = B_ * 2 * N_;           // 65536 query slots (both dirs)
constexpr int MBLOCKS = NQTOT / 256;           // 256 merge blocks
constexpr int NSETS   = B_ * 2;                // 8 point-sets (pred/tgt per batch)
}

typedef unsigned long long ull;

__device__ __forceinline__ ull fx2_add(ull a, ull b) {
    ull r; asm("add.rn.f32x2 %0, %1, %2;" : "=l"(r) : "l"(a), "l"(b)); return r;
}
__device__ __forceinline__ ull fx2_mul(ull a, ull b) {
    ull r; asm("mul.rn.f32x2 %0, %1, %2;" : "=l"(r) : "l"(a), "l"(b)); return r;
}
__device__ __forceinline__ ull fx2_fma(ull a, ull b, ull c) {
    ull r; asm("fma.rn.f32x2 %0, %1, %2, %3;" : "=l"(r) : "l"(a), "l"(b), "l"(c)); return r;
}
__device__ __forceinline__ ull pack2(float lo, float hi) {
    return (ull)__float_as_uint(lo) | ((ull)__float_as_uint(hi) << 32);
}
__device__ __forceinline__ ull dupf(float v) {
    unsigned u = __float_as_uint(v);
    return (ull)u | ((ull)u << 32);
}

// Scratch (static device globals: no allocation).
__device__ float    g_knn[NSPLIT * NQTOT * KNN];   // 8 MB: sorted partial d^2 lists
__device__ float    g_partials[MBLOCKS];
__device__ unsigned g_perm[NSETS][N_];             // sorted (morton<<13 | idx) keys

// ---------------- Morton sort (deterministic bitonic, one block per set) ---

__device__ __forceinline__ unsigned quant5(float x) {
    float q = (x + 4.0f) * 4.0f;                 // cell = 0.25 over [-4,4)
    q = fminf(fmaxf(q, 0.0f), 31.0f);
    return (unsigned)q;
}
__device__ __forceinline__ unsigned part5(unsigned v) {
    unsigned r = (v & 1u);
    r |= (v & 2u)  << 2;    // bit1 -> 3
    r |= (v & 4u)  << 4;    // bit2 -> 6
    r |= (v & 8u)  << 6;    // bit3 -> 9
    r |= (v & 16u) << 8;    // bit4 -> 12
    return r;
}

__global__ __launch_bounds__(1024)
void morton_sort_kernel(const float* __restrict__ src,
                        const float* __restrict__ tgt,
                        const float* __restrict__ flow)
{
    __shared__ unsigned sk[N_];                  // 32 KB
    const int set = blockIdx.x;                  // b*2 + s (s=0: pred, s=1: tgt)
    const int b   = set >> 1;
    const int s   = set & 1;
    const float* __restrict__ sb = src  + (size_t)b * N_ * 3;
    const float* __restrict__ tb = tgt  + (size_t)b * N_ * 3;
    const float* __restrict__ fb = flow + (size_t)b * N_ * 3;

    for (int i = threadIdx.x; i < N_; i += 1024) {
        float x, y, z;
        if (s == 0) {
            x = sb[3 * i + 0] + fb[3 * i + 0];
            y = sb[3 * i + 1] + fb[3 * i + 1];
            z = sb[3 * i + 2] + fb[3 * i + 2];
        } else {
            x = tb[3 * i + 0]; y = tb[3 * i + 1]; z = tb[3 * i + 2];
        }
        const unsigned m = part5(quant5(x)) | (part5(quant5(y)) << 1)
                         | (part5(quant5(z)) << 2);          // 15 bits
        sk[i] = (m << 13) | (unsigned)i;                      // unique key
    }
    __syncthreads();

    for (int k = 2; k <= N_; k <<= 1) {
        for (int j = k >> 1; j > 0; j >>= 1) {
            for (int t = threadIdx.x; t < N_; t += 1024) {
                const int p = t ^ j;
                if (p > t) {                       // each pair handled once
                    const unsigned a = sk[t], c = sk[p];
                    const bool up = ((t & k) == 0);
                    if ((a > c) == up) { sk[t] = c; sk[p] = a; }
                }
            }
            __syncthreads();
        }
    }

    for (int i = threadIdx.x; i < N_; i += 1024)
        g_perm[set][i] = sk[i];
}

// ---------------- main KNN kernel ------------------------------------------

__global__ __launch_bounds__(THREADS)
void chamfer_knn_kernel(const float* __restrict__ src,
                        const float* __restrict__ tgt,
                        const float* __restrict__ flow)
{
    // candidate tile: per candidate {-x,-x,-y,-y} (16B, LDS.128) + {-z,-z} (8B)
    __shared__ __align__(16) ulonglong2 sXY[CHUNK];   // 16 KB
    __shared__ __align__(16) ull        sZ[CHUNK];    //  8 KB

    const int tid    = threadIdx.x;
    const int bi     = blockIdx.x;
    const int split  = bi & (NSPLIT - 1);
    const int rest   = bi / NSPLIT;
    const int chunkq = rest % QCHUNKS;       // which 256-query slice (sorted order)
    const int bd     = rest / QCHUNKS;       // b*2 + dir
    const int dir    = bd & 1;               // 0: pred->tgt, 1: tgt->pred
    const int b      = bd >> 1;

    const float* __restrict__ sbase = src  + (size_t)b * N_ * 3;
    const float* __restrict__ tbase = tgt  + (size_t)b * N_ * 3;
    const float* __restrict__ fbase = flow + (size_t)b * N_ * 3;

    // ---- load this thread's two queries through the Morton permutation ----
    float qx[QPT], qy[QPT], qz[QPT];
#pragma unroll
    for (int u = 0; u < QPT; ++u) {
        const int slot = chunkq * QPB + u * THREADS + tid;
        const int qi   = (int)(g_perm[bd][slot] & (unsigned)(N_ - 1));
        if (dir == 0) {            // query = pc_pred = src + flow
            qx[u] = sbase[3 * qi + 0] + fbase[3 * qi + 0];
            qy[u] = sbase[3 * qi + 1] + fbase[3 * qi + 1];
            qz[u] = sbase[3 * qi + 2] + fbase[3 * qi + 2];
        } else {                   // query = tgt
            qx[u] = tbase[3 * qi + 0];
            qy[u] = tbase[3 * qi + 1];
            qz[u] = tbase[3 * qi + 2];
        }
    }
    const ull qx2 = pack2(qx[0], qx[1]);
    const ull qy2 = pack2(qy[0], qy[1]);
    const ull qz2 = pack2(qz[0], qz[1]);

    // ---- per-query sorted min-8 of squared distances (ascending) ----
    float h0[KNN], h1[KNN];
#pragma unroll
    for (int i = 0; i < KNN; ++i) { h0[i] = 3.0e38f; h1[i] = 3.0e38f; }
    unsigned t0 = __float_as_uint(3.0e38f);   // bits of h0[7]
    unsigned t1 = t0;                          // bits of h1[7]

    for (int ch = 0; ch < NCHUNK; ++ch) {
        __syncthreads();   // previous tile fully consumed
        const int gbase = (split * CANDS + ch * CHUNK) * 3;
        for (int t = tid; t < CHUNK * 3; t += THREADS) {
            float v;
            if (dir == 0) v = -tbase[gbase + t];                       // cands = tgt
            else          v = -(sbase[gbase + t] + fbase[gbase + t]);  // cands = pred
            const int p = t / 3;
            const int c = t - 3 * p;
            const ull d = dupf(v);
            if (c == 0)      sXY[p].x = d;
            else if (c == 1) sXY[p].y = d;
            else             sZ[p]    = d;
        }
        __syncthreads();

#pragma unroll 4
        for (int j = 0; j < CHUNK; ++j) {
            const ulonglong2 cxy = sXY[j];    // broadcast LDS.128 (pre-negated)
            const ull cz = sZ[j];             // broadcast LDS.64
            const ull dx = fx2_add(qx2, cxy.x);
            const ull dy = fx2_add(qy2, cxy.y);
            const ull dz = fx2_add(qz2, cz);
            const ull d2 = fx2_fma(dx, dx, fx2_fma(dy, dy, fx2_mul(dz, dz)));
            const unsigned d0 = (unsigned)d2;          // low half  (query 0)
            const unsigned d1 = (unsigned)(d2 >> 32);  // high half (query 1)
            // nonnegative floats: uint compare == float compare (alu pipe)
            if (__builtin_expect(d0 < t0, 0)) {
                float v = __uint_as_float(d0);
#pragma unroll
                for (int i = KNN - 1; i > 0; --i) {
                    const float hp = h0[i - 1];
                    h0[i] = fmaxf(hp, v);
                    v     = fminf(hp, v);
                }
                h0[0] = v;
                t0 = __float_as_uint(h0[KNN - 1]);
            }
            if (__builtin_expect(d1 < t1, 0)) {
                float v = __uint_as_float(d1);
#pragma unroll
                for (int i = KNN - 1; i > 0; --i) {
                    const float hp = h1[i - 1];
                    h1[i] = fmaxf(hp, v);
                    v     = fminf(hp, v);
                }
                h1[0] = v;
                t1 = __float_as_uint(h1[KNN - 1]);
            }
        }
    }

    // ---- write sorted partial lists (d^2) keyed by sorted slot ----
    const int qg0 = bd * N_ + chunkq * QPB + tid;            // slot 0 global id
    const int qg1 = qg0 + THREADS;                           // slot 1 global id
    float4* out0 = reinterpret_cast<float4*>(g_knn + ((size_t)split * NQTOT + qg0) * KNN);
    float4* out1 = reinterpret_cast<float4*>(g_knn + ((size_t)split * NQTOT + qg1) * KNN);
    out0[0] = make_float4(h0[0], h0[1], h0[2], h0[3]);
    out0[1] = make_float4(h0[4], h0[5], h0[6], h0[7]);
    out1[0] = make_float4(h1[0], h1[1], h1[2], h1[3]);
    out1[1] = make_float4(h1[4], h1[5], h1[6], h1[7]);
}

// --- exact branchless merge helpers ---
// halver: m[i] = min(a[i], b[7-i]); if a,b ascending, m = 8 smallest of a∪b (bitonic).
__device__ __forceinline__ void halver8(const float* __restrict__ a,
                                        const float* __restrict__ b,
                                        float* __restrict__ m)
{
#pragma unroll
    for (int i = 0; i < 8; ++i) m[i] = fminf(a[i], b[7 - i]);
}
// sort a bitonic 8-sequence ascending (3 compare-exchange stages).
__device__ __forceinline__ void bitonic_sort8(float* __restrict__ m)
{
#pragma unroll
    for (int st = 4; st > 0; st >>= 1)
#pragma unroll
        for (int i = 0; i < 8; ++i)
            if ((i & st) == 0) {
                const float lo = fminf(m[i], m[i + st]);
                const float hi = fmaxf(m[i], m[i + st]);
                m[i] = lo; m[i + st] = hi;
            }
}

// Merge 4 sorted partial top-8 lists per query, sum sqrt, deterministic reduce.
__global__ __launch_bounds__(256)
void chamfer_merge_kernel()
{
    const int qg = blockIdx.x * 256 + threadIdx.x;
    float L[NSPLIT][KNN];
#pragma unroll
    for (int sp = 0; sp < NSPLIT; ++sp) {
        const float4* p = reinterpret_cast<const float4*>(
            g_knn + ((size_t)sp * NQTOT + qg) * KNN);
        const float4 v0 = p[0], v1 = p[1];
        L[sp][0] = v0.x; L[sp][1] = v0.y; L[sp][2] = v0.z; L[sp][3] = v0.w;
        L[sp][4] = v1.x; L[sp][5] = v1.y; L[sp][6] = v1.z; L[sp][7] = v1.w;
    }

    float m01[8], m23[8], fin[8];
    halver8(L[0], L[1], m01); bitonic_sort8(m01);
    halver8(L[2], L[3], m23); bitonic_sort8(m23);
    halver8(m01, m23, fin);   // 8 smallest of all 32 (multiset; order irrelevant)

    float s = 0.0f;
#pragma unroll
    for (int i = 0; i < 8; ++i) s += sqrtf(fin[i]);

#pragma unroll
    for (int o = 16; o > 0; o >>= 1)
        s += __shfl_down_sync(0xffffffffu, s, o);

    __shared__ float ws[8];
    if ((threadIdx.x & 31) == 0) ws[threadIdx.x >> 5] = s;
    __syncthreads();
    if (threadIdx.x == 0) {
        float t = 0.0f;
#pragma unroll
        for (int i = 0; i < 8; ++i) t += ws[i];
        g_partials[blockIdx.x] = t;
    }
}

__global__ __launch_bounds__(MBLOCKS)
void chamfer_reduce_kernel(float* __restrict__ out)
{
    const int t = threadIdx.x;
    float v = g_partials[t];
#pragma unroll
    for (int o = 16; o > 0; o >>= 1)
        v += __shfl_down_sync(0xffffffffu, v, o);

    __shared__ float ws[MBLOCKS / 32];
    if ((t & 31) == 0) ws[t >> 5] = v;
    __syncthreads();
    if (t == 0) {
        float s = 0.0f;
#pragma unroll
        for (int i = 0; i < MBLOCKS / 32; ++i) s += ws[i];
        out[0] = s * (1.0f / (float)(B_ * N_ * KNN));
    }
}

extern "C" void kernel_launch(void* const* d_in, const int* in_sizes, int n_in,
                              void* d_out, int out_size)
{
    (void)in_sizes; (void)n_in; (void)out_size;
    const float* src  = (const float*)d_in[0];
    const float* tgt  = (const float*)d_in[1];
    const float* flow = (const float*)d_in[2];
    float* out = (float*)d_out;

    morton_sort_kernel<<<NSETS, 1024>>>(src, tgt, flow);
    chamfer_knn_kernel<<<BLOCKS, THREADS>>>(src, tgt, flow);
    chamfer_merge_kernel<<<MBLOCKS, 256>>>();
    chamfer_reduce_kernel<<<1, MBLOCKS>>>(out);
}